// round 1
// baseline (speedup 1.0000x reference)
#include <cuda_runtime.h>
#include <cstdint>

// real, pred: [128, 8192, 8] fp32. Row = 8 classes.
// loss = 1 - mean_over_rows( all_c( (pred>0.5) == real ) )

static constexpr int B = 128;
static constexpr int L = 8192;
static constexpr int C = 8;
static constexpr long long NROWS = (long long)B * L;   // 1,048,576
static constexpr int TPB = 256;
static constexpr int RPT = 4;                           // rows per thread
static constexpr int BLOCKS = (int)(NROWS / (TPB * RPT)); // 1024

__device__ unsigned int g_count;

__global__ void zero_kernel() { g_count = 0u; }

__device__ __forceinline__ bool row_ok(float4 r0, float4 r1, float4 p0, float4 p1) {
    // real is exactly 0.0f or 1.0f; predicted label = (pred > 0.5f)
    bool ok =
        ((p0.x > 0.5f) == (r0.x != 0.0f)) &
        ((p0.y > 0.5f) == (r0.y != 0.0f)) &
        ((p0.z > 0.5f) == (r0.z != 0.0f)) &
        ((p0.w > 0.5f) == (r0.w != 0.0f)) &
        ((p1.x > 0.5f) == (r1.x != 0.0f)) &
        ((p1.y > 0.5f) == (r1.y != 0.0f)) &
        ((p1.z > 0.5f) == (r1.z != 0.0f)) &
        ((p1.w > 0.5f) == (r1.w != 0.0f));
    return ok;
}

__global__ __launch_bounds__(TPB) void count_kernel(
    const float4* __restrict__ real4, const float4* __restrict__ pred4)
{
    const int stride = TPB * BLOCKS;               // rows covered per sweep
    int base = blockIdx.x * TPB + threadIdx.x;

    int local = 0;
#pragma unroll
    for (int i = 0; i < RPT; i++) {
        int row = base + i * stride;
        // 2 x float4 per tensor per row; adjacent lanes -> adjacent rows (coalesced)
        float4 r0 = real4[2 * row + 0];
        float4 r1 = real4[2 * row + 1];
        float4 p0 = pred4[2 * row + 0];
        float4 p1 = pred4[2 * row + 1];
        local += (int)row_ok(r0, r1, p0, p1);
    }

    // warp reduce
    local = __reduce_add_sync(0xFFFFFFFFu, local);

    __shared__ int smem[TPB / 32];
    if ((threadIdx.x & 31) == 0) smem[threadIdx.x >> 5] = local;
    __syncthreads();
    if (threadIdx.x == 0) {
        int t = 0;
#pragma unroll
        for (int w = 0; w < TPB / 32; w++) t += smem[w];
        atomicAdd(&g_count, (unsigned int)t);
    }
}

__global__ void finalize_kernel(float* out) {
    *out = 1.0f - (float)g_count * (1.0f / (float)NROWS);
}

extern "C" void kernel_launch(void* const* d_in, const int* in_sizes, int n_in,
                              void* d_out, int out_size) {
    const float4* real4 = (const float4*)d_in[0];
    const float4* pred4 = (const float4*)d_in[1];
    float* out = (float*)d_out;

    zero_kernel<<<1, 1>>>();
    count_kernel<<<BLOCKS, TPB>>>(real4, pred4);
    finalize_kernel<<<1, 1>>>(out);
}